// round 17
// baseline (speedup 1.0000x reference)
#include <cuda_runtime.h>
#include <cstddef>
#include <cstdint>

#define B_   128
#define T_   1024
#define NI_  64
#define NH_  512
#define DT_C 0.01f

#define S_   16    // N-slices per batch group (CTAs per sync group)
#define NS_  32    // hidden cols per slice
#define G_   8     // batch groups
#define MG_  16    // batch rows per group

typedef unsigned long long ull;

// __device__ scratch (allocation-free rule)
__device__ float g_i2h[(size_t)B_ * T_ * NH_];     // tanh(x @ x2h), [B][T][NH]
__device__ float g_hyT[G_][NH_][MG_];              // hy exchange, [k][m]
__device__ float g_zT [G_][NH_][MG_];              // z  exchange, [k][m]
__device__ int   g_flagH[G_][S_];
__device__ int   g_flagZ[G_][S_];

// ---- scoped release/acquire flag ops ----
__device__ __forceinline__ void st_release_gpu(int* p, int v) {
    asm volatile("st.release.gpu.b32 [%0], %1;" :: "l"(p), "r"(v) : "memory");
}
__device__ __forceinline__ int ld_acquire_gpu(const int* p) {
    int v;
    asm volatile("ld.acquire.gpu.b32 %0, [%1];" : "=r"(v) : "l"(p) : "memory");
    return v;
}

// ---- packed fp32x2 FMA (sm_10x; PTX-only, no C++ auto-fuse) ----
__device__ __forceinline__ ull ffma2(ull a, ull b, ull c) {
    ull d;
    asm("fma.rn.f32x2 %0, %1, %2, %3;" : "=l"(d) : "l"(a), "l"(b), "l"(c));
    return d;
}
__device__ __forceinline__ ull pack2(float x) {
    ull d;
    asm("mov.b64 %0, {%1, %1};" : "=l"(d) : "f"(x));
    return d;
}

// ---- cp.async 16B (generic proxy, L2-sourced) ----
__device__ __forceinline__ void cpa16(void* smem_dst, const void* gsrc) {
    unsigned sa = (unsigned)__cvta_generic_to_shared(smem_dst);
    asm volatile("cp.async.cg.shared.global [%0], [%1], 16;" :: "r"(sa), "l"(gsrc) : "memory");
}
__device__ __forceinline__ void cpa_wait_all() {
    asm volatile("cp.async.commit_group;\n\tcp.async.wait_group 0;" ::: "memory");
}

// ---------------------------------------------------------------------------
// i2h = tanh(x @ x2h).  x: [B*T, 64], x2h: [64, 512].
// Block (0,0) also resets the scan flags (stream order precedes k_scan).
// ---------------------------------------------------------------------------
__global__ __launch_bounds__(256) void k_i2h(const float* __restrict__ x,
                                             const float* __restrict__ x2h) {
    __shared__ float xsT[64][64];
    __shared__ float ws[64][64];
    int row0 = blockIdx.y * 64;
    int col0 = blockIdx.x * 64;
    int tid  = threadIdx.x;

    if (blockIdx.x == 0 && blockIdx.y == 0 && tid < G_ * S_) {
        ((int*)g_flagH)[tid] = 0;
        ((int*)g_flagZ)[tid] = 0;
    }

    const float4* xsrc = reinterpret_cast<const float4*>(x + (size_t)row0 * NI_);
    for (int i = tid; i < 1024; i += 256) {
        float4 v = xsrc[i];
        int m = i >> 4;
        int k = (i & 15) * 4;
        xsT[k + 0][m] = v.x; xsT[k + 1][m] = v.y;
        xsT[k + 2][m] = v.z; xsT[k + 3][m] = v.w;
    }
    for (int i = tid; i < 1024; i += 256) {
        int k = i >> 4;
        int c = (i & 15) * 4;
        float4 v = *reinterpret_cast<const float4*>(x2h + (size_t)k * NH_ + col0 + c);
        *reinterpret_cast<float4*>(&ws[k][c]) = v;
    }
    __syncthreads();

    int tx = tid & 15, ty = tid >> 4;
    int m0 = ty * 4, n0 = tx * 4;
    float acc[4][4] = {};
    #pragma unroll 4
    for (int k = 0; k < 64; k++) {
        float4 a = *reinterpret_cast<float4*>(&xsT[k][m0]);
        float4 b = *reinterpret_cast<float4*>(&ws[k][n0]);
        float av[4] = {a.x, a.y, a.z, a.w};
        float bv[4] = {b.x, b.y, b.z, b.w};
        #pragma unroll
        for (int i = 0; i < 4; i++)
            #pragma unroll
            for (int j = 0; j < 4; j++)
                acc[i][j] = fmaf(av[i], bv[j], acc[i][j]);
    }
    #pragma unroll
    for (int i = 0; i < 4; i++) {
        float4 o;
        o.x = tanhf(acc[i][0]); o.y = tanhf(acc[i][1]);
        o.z = tanhf(acc[i][2]); o.w = tanhf(acc[i][3]);
        *reinterpret_cast<float4*>(&g_i2h[(size_t)(row0 + m0 + i) * NH_ + col0 + n0]) = o;
    }
}

// ---------------------------------------------------------------------------
// Persistent scan: 128 CTAs = 8 batch groups x 16 N-slices, 512 threads.
// Weights SMEM-resident. GEMV micro-tile 4r x 4c x K32 with packed f32x2
// FMA (pairs across cols; weight LDS.128 reinterprets as 2x b64 free).
// Sync: one warp polls 16 flags (acquire); publish = direct scattered stcg
// -> bar -> lone st.release. Gathers via cp.async.cg.
//
// SMEM floats: Ws4 @0 (16384) | WTs @16384 (18432, [k][36]) |
//              xbuf @34816 (8192, [k][m] f4) | parts @43008 (9216)
//              => 52224 floats = 208896 B
// ---------------------------------------------------------------------------
#define SMEM_BYTES 208896

__global__ __launch_bounds__(512, 1) void k_scan(const float* __restrict__ W,
                                                 const float* __restrict__ bias,
                                                 float* __restrict__ out,
                                                 int write_final) {
    extern __shared__ float sm[];
    float4*     Ws4   = reinterpret_cast<float4*>(sm);            // [k*8 + ng]
    ulonglong2* Wsu   = reinterpret_cast<ulonglong2*>(sm);        // same bytes
    float*      WTs   = sm + 16384;                               // [k*36 + r]
    float*      xbuf  = sm + 34816;                               // [k][m]
    float4*     xb4   = reinterpret_cast<float4*>(xbuf);          // [k*4 + mq]
    float*      parts = sm + 43008;                               // [(kc*16+mr)*36 + n]

    const int tid = threadIdx.x;
    const int s   = blockIdx.x & 15;   // N-slice
    const int g   = blockIdx.x >> 4;   // batch group

    // GEMV micro-tile mapping: warp = one K-chunk of 32
    const int kc = tid >> 5;           // K-chunk 0..15
    const int mq = (tid >> 3) & 3;     // row quad 0..3
    const int ng = tid & 7;            // col group 0..7
    const int k0 = kc << 5;

    // state mapping: thread owns (m, n)
    const int m = tid >> 5;
    const int n = tid & 31;

    // ---- prologue: load weight slices into SMEM ----
    {
        const float4* W4 = reinterpret_cast<const float4*>(W);
        #pragma unroll
        for (int j = 0; j < 8; j++) {           // Ws[k][c] = W[k][s*32+c]
            int f4 = tid + j * 512;
            int k  = f4 >> 3, c = f4 & 7;
            Ws4[k * 8 + c] = W4[(size_t)k * 128 + s * 8 + c];
        }
        #pragma unroll
        for (int j = 0; j < 8; j++) {           // WTs[k][r] = W[s*32+r][k]
            int f4  = tid + j * 512;
            int r   = f4 >> 7;
            int kc4 = f4 & 127;
            float4 v = W4[(size_t)(s * 32 + r) * 128 + kc4];
            int k = kc4 * 4;
            WTs[(k + 0) * 36 + r] = v.x;
            WTs[(k + 1) * 36 + r] = v.y;
            WTs[(k + 2) * 36 + r] = v.z;
            WTs[(k + 3) * 36 + r] = v.w;
        }
    }
    const float bj = __ldg(bias + s * NS_ + n);
    float hy = 0.f, hz = 0.f;
    __syncthreads();

    const size_t io_base = ((size_t)(g * MG_ + m) * T_) * NH_ + s * NS_ + n;
    const float4* hySrc = reinterpret_cast<const float4*>(&g_hyT[g][0][0]);
    const float4* zSrc  = reinterpret_cast<const float4*>(&g_zT [g][0][0]);
    int* const fH = (tid < S_) ? &g_flagH[g][tid] : nullptr;
    int* const fZ = (tid < S_) ? &g_flagZ[g][tid] : nullptr;
    const float* wtB = WTs + ng * 4;           // phase-2 weight base (16B aligned)

    for (int t = 0; t < T_; t++) {
        const float inp = __ldg(&g_i2h[io_base + (size_t)t * NH_]);

        if (t == 0) {
            // hy=0 => z[k] = tanh(bias[k]) for all m; fill locally, skip phase1.
            #pragma unroll
            for (int j = 0; j < 4; j++) {
                int f4 = tid + j * 512;            // [k*4 + mq]
                float v = tanhf(__ldg(bias + (f4 >> 2)));
                xb4[f4] = make_float4(v, v, v, v);
            }
            __syncthreads();
        } else {
            // ---- wait for all hy slices (single-warp poll) + async gather --
            if (tid < S_) { while (ld_acquire_gpu(fH) < t) { } }
            __syncthreads();
            #pragma unroll
            for (int j = 0; j < 4; j++) {
                int f4 = tid + j * 512;
                cpa16(&xb4[f4], hySrc + f4);
            }
            cpa_wait_all();
            __syncthreads();

            // ---- phase 1: a = hy @ W[:, slice]  (f32x2, pairs across cols) -
            ull a00 = 0ull, a01 = 0ull, a10 = 0ull, a11 = 0ull;
            ull a20 = 0ull, a21 = 0ull, a30 = 0ull, a31 = 0ull;
            #pragma unroll
            for (int i = 0; i < 32; i++) {
                const int k = k0 + i;
                ulonglong2 w = Wsu[k * 8 + ng];     // {w0,w1},{w2,w3}
                float4 h = xb4[k * 4 + mq];
                ull h0 = pack2(h.x), h1 = pack2(h.y);
                ull h2 = pack2(h.z), h3 = pack2(h.w);
                a00 = ffma2(h0, w.x, a00); a01 = ffma2(h0, w.y, a01);
                a10 = ffma2(h1, w.x, a10); a11 = ffma2(h1, w.y, a11);
                a20 = ffma2(h2, w.x, a20); a21 = ffma2(h2, w.y, a21);
                a30 = ffma2(h3, w.x, a30); a31 = ffma2(h3, w.y, a31);
            }
            {
                float* pb = &parts[(kc * 16 + mq * 4) * 36 + ng * 4];
                *reinterpret_cast<ull*>(pb + 0 * 36)     = a00;
                *reinterpret_cast<ull*>(pb + 0 * 36 + 2) = a01;
                *reinterpret_cast<ull*>(pb + 1 * 36)     = a10;
                *reinterpret_cast<ull*>(pb + 1 * 36 + 2) = a11;
                *reinterpret_cast<ull*>(pb + 2 * 36)     = a20;
                *reinterpret_cast<ull*>(pb + 2 * 36 + 2) = a21;
                *reinterpret_cast<ull*>(pb + 3 * 36)     = a30;
                *reinterpret_cast<ull*>(pb + 3 * 36 + 2) = a31;
            }
            __syncthreads();

            // reduce 16 partials, tanh, publish z directly (scattered stcg)
            {
                float a = 0.f;
                #pragma unroll
                for (int q = 0; q < 16; q++) a += parts[(q * 16 + m) * 36 + n];
                __stcg(&g_zT[g][s * NS_ + n][m], tanhf(a + bj));
            }
            __syncthreads();
            if (tid == 0) st_release_gpu(&g_flagZ[g][s], t + 1);

            // ---- wait for all z slices + async gather ----
            if (tid < S_) { while (ld_acquire_gpu(fZ) < t + 1) { } }
            __syncthreads();
            #pragma unroll
            for (int j = 0; j < 4; j++) {
                int f4 = tid + j * 512;
                cpa16(&xb4[f4], zSrc + f4);
            }
            cpa_wait_all();
            __syncthreads();
        }

        // ---- phase 2: rec = z @ WT[:, slice]  (f32x2) ----
        {
            ull a00 = 0ull, a01 = 0ull, a10 = 0ull, a11 = 0ull;
            ull a20 = 0ull, a21 = 0ull, a30 = 0ull, a31 = 0ull;
            #pragma unroll
            for (int i = 0; i < 32; i++) {
                const int k = k0 + i;
                ulonglong2 w = *reinterpret_cast<const ulonglong2*>(wtB + k * 36);
                float4 z = xb4[k * 4 + mq];
                ull z0 = pack2(z.x), z1 = pack2(z.y);
                ull z2 = pack2(z.z), z3 = pack2(z.w);
                a00 = ffma2(z0, w.x, a00); a01 = ffma2(z0, w.y, a01);
                a10 = ffma2(z1, w.x, a10); a11 = ffma2(z1, w.y, a11);
                a20 = ffma2(z2, w.x, a20); a21 = ffma2(z2, w.y, a21);
                a30 = ffma2(z3, w.x, a30); a31 = ffma2(z3, w.y, a31);
            }
            float* pb = &parts[(kc * 16 + mq * 4) * 36 + ng * 4];
            *reinterpret_cast<ull*>(pb + 0 * 36)     = a00;
            *reinterpret_cast<ull*>(pb + 0 * 36 + 2) = a01;
            *reinterpret_cast<ull*>(pb + 1 * 36)     = a10;
            *reinterpret_cast<ull*>(pb + 1 * 36 + 2) = a11;
            *reinterpret_cast<ull*>(pb + 2 * 36)     = a20;
            *reinterpret_cast<ull*>(pb + 2 * 36 + 2) = a21;
            *reinterpret_cast<ull*>(pb + 3 * 36)     = a30;
            *reinterpret_cast<ull*>(pb + 3 * 36 + 2) = a31;
        }
        __syncthreads();

        // reduce + state update (GAMMA = EPSILON = 1), publish hy directly
        {
            float rr = 0.f;
            #pragma unroll
            for (int q = 0; q < 16; q++) rr += parts[(q * 16 + m) * 36 + n];
            hz += DT_C * (inp - rr - hy - hz);
            hy += DT_C * hz;
            __stcg(&g_hyT[g][s * NS_ + n][m], hy);
        }
        __syncthreads();
        if (tid == 0) st_release_gpu(&g_flagH[g][s], t + 1);

        // out store AFTER release: off the group-wide critical path
        out[io_base + (size_t)t * NH_] = hy;
    }

    if (write_final) {
        out[(size_t)B_ * T_ * NH_ + (size_t)(g * MG_ + m) * NH_ + s * NS_ + n] = hy;
    }
}

// ---------------------------------------------------------------------------
// Launch. Inputs: x [128,1024,64] f32, x2h [64,512] f32, h2h [512,512] f32,
// bias [512] f32. Output f32: all_states [128,1024,512] (+ hy_f [128,512]).
// ---------------------------------------------------------------------------
extern "C" void kernel_launch(void* const* d_in, const int* in_sizes, int n_in,
                              void* d_out, int out_size) {
    const float* x    = (const float*)d_in[0];
    const float* x2h  = (const float*)d_in[1];
    const float* h2h  = (const float*)d_in[2];
    const float* bias = (const float*)d_in[3];
    float* out = (float*)d_out;

    const long long states_elems = (long long)B_ * T_ * NH_;
    int write_final = ((long long)out_size >= states_elems + (long long)B_ * NH_) ? 1 : 0;

    cudaFuncSetAttribute(k_scan, cudaFuncAttributeMaxDynamicSharedMemorySize, SMEM_BYTES);

    k_i2h<<<dim3(NH_ / 64, (B_ * T_) / 64), 256>>>(x, x2h);
    k_scan<<<G_ * S_, 512, SMEM_BYTES>>>(h2h, bias, out, write_final);
}